// round 12
// baseline (speedup 1.0000x reference)
#include <cuda_runtime.h>
#include <math.h>

#define BT 512   // threads per block (main kernel)
#define M  8     // batch rows per block

// ---------------- problem constants ----------------
constexpr int Bsz = 1024, Tsz = 256, DIN = 128;
constexpr int NH0 = 269, NH1 = 179, NH2 = 64;
constexpr int CAT0 = DIN + NH0;   // 397
constexpr int CAT1 = NH0 + NH1;   // 448
constexpr int CAT2 = NH1 + NH2;   // 243
constexpr int CATP0 = 400, CATP1 = 448, CATP2 = 244;  // padded k
constexpr int OUTD = 64;
constexpr long long PRED_ELEMS = (long long)Bsz * Tsz * OUTD;

// gate strides in the per-gate weight arrays
constexpr int GS0 = CATP0 * NH0;   // 107600
constexpr int GS1 = CATP1 * NH1;   // 80192
constexpr int GS2 = CATP2 * NH2;   // 15616

// L0 tail: 13 units x 16 chunks of 25 k (on crew A, 208 threads)
constexpr int T0_CH = 16, T0_KL = 25;

// ---------------- device scratch ----------------
__device__ float g_W0[3 * GS0];   // [gate][k][j], gates: ff1, ff2, ta+tb
__device__ float g_W1[3 * GS1];
__device__ float g_W2[3 * GS2];
__device__ float g_B0[3 * NH0];
__device__ float g_B1[3 * NH1];
__device__ float g_B2[3 * NH2];
__device__ int   g_fmt[3];

// ---------------- mask dtype detection (unchanged, known-good) ----------------
__global__ void detect_kernel(const void* m0, int n0, const void* m1, int n1,
                              const void* m2, int n2) {
    const void* p = (blockIdx.x == 0) ? m0 : (blockIdx.x == 1) ? m1 : m2;
    int n = (blockIdx.x == 0) ? n0 : (blockIdx.x == 1) ? n1 : n2;
    __shared__ int fl;
    if (threadIdx.x == 0) fl = 0;
    __syncthreads();
    int nw = n >> 2;
    const unsigned* w = (const unsigned*)p;
    int loc = 0;
    for (int i = threadIdx.x; i < nw; i += blockDim.x) {
        unsigned v = w[i];
        if (v == 0x3F800000u) loc |= 1;
        else if (v == 0x3F803F80u || v == 0x00003F80u) loc |= 2;
        else if (v != 0u && v != 1u) loc |= 4;
    }
    atomicOr(&fl, loc);
    __syncthreads();
    if (threadIdx.x == 0) {
        int f = fl, fmt;
        if (f & 2) fmt = 3;
        else if (f & 1) fmt = 0;
        else if (f & 4) fmt = 2;
        else fmt = 1;
        g_fmt[blockIdx.x] = fmt;
    }
}

__device__ __forceinline__ bool maskbit(const void* p, int fmt, int idx) {
    switch (fmt) {
        case 0: return ((const float*)p)[idx] != 0.0f;
        case 1: return ((const int*)p)[idx] != 0;
        case 3: return ((const unsigned short*)p)[idx] != 0;
        default: return ((const unsigned char*)p)[idx] != 0;
    }
}

// ---------------- fused weight prep (all 3 layers, one launch) ----------------
__device__ __forceinline__ void prep_elem(
    long long idx, const float* w1, const float* w2,
    const float* wa, const float* wb,
    const float* b1, const float* b2, const float* ba, const float* bb,
    const void* mask, int fmt, int CAT, int CATP, int NH,
    float* W, float* Bc) {
    long long per = (long long)CATP * NH;
    int g = (int)(idx / per);
    long long rem = idx - (long long)g * per;
    int k = (int)(rem / NH);
    int j = (int)(rem - (long long)k * NH);
    float v = 0.0f;
    if (k < CAT) {
        if (g == 2) {
            v = wa[j * CAT + k] + wb[j * CAT + k];
        } else {
            v = (g == 0) ? w1[j * CAT + k] : w2[j * CAT + k];
            if (!maskbit(mask, fmt, j * CAT + k)) v = 0.0f;
        }
    }
    W[idx] = v;
    if (k == 0)
        Bc[g * NH + j] = (g == 0) ? b1[j] : (g == 1) ? b2[j] : (ba[j] + bb[j]);
}

__global__ void prep_all(
    const float* f10, const float* f20, const float* ta0, const float* tb0,
    const float* b10, const float* b20, const float* ba0, const float* bb0,
    const float* f11, const float* f21, const float* ta1, const float* tb1,
    const float* b11, const float* b21, const float* ba1, const float* bb1,
    const float* f12, const float* f22, const float* ta2, const float* tb2,
    const float* b12, const float* b22, const float* ba2, const float* bb2,
    const void* m0, const void* m1, const void* m2) {
    const long long N0 = 3LL * GS0, N1 = 3LL * GS1, N2 = 3LL * GS2;
    const long long total = N0 + N1 + N2;
    for (long long idx = (long long)blockIdx.x * blockDim.x + threadIdx.x;
         idx < total; idx += (long long)gridDim.x * blockDim.x) {
        if (idx < N0) {
            prep_elem(idx, f10, f20, ta0, tb0, b10, b20, ba0, bb0,
                      m0, g_fmt[0], CAT0, CATP0, NH0, g_W0, g_B0);
        } else if (idx < N0 + N1) {
            prep_elem(idx - N0, f11, f21, ta1, tb1, b11, b21, ba1, bb1,
                      m1, g_fmt[1], CAT1, CATP1, NH1, g_W1, g_B1);
        } else {
            prep_elem(idx - N0 - N1, f12, f22, ta2, tb2, b12, b22, ba2, bb2,
                      m2, g_fmt[2], CAT2, CATP2, NH2, g_W2, g_B2);
        }
    }
}

// ---------------- main persistent kernel ----------------
struct SM {
    float xt0[2][CATP0][M];       // [buf][ x(128) | h0(269) | pad ]
    float xt1[CATP1][M];          // [ n0(269) | h1(179) ]
    float xt2[CATP2][M];          // [ n1(179) | h2(64) | pad ]
    float P0x[T0_CH][13][3][M];   // L0 tail partials (crew A -> boundary)
    union {                        // crew-B scratch (sequential use, nbar-ordered)
        float p1[4][NH1][3][M];    // L1 partials [kq][j][gate][row]
        float p2[4][64][3][M];     // L2 partials
    } P;
    float fcT[OUTD * OUTD];       // fcT[m*64+o] = fc_w[o][m]
    float fcb[OUTD];
    float b0[3 * NH0];
    float b1[3 * NH1];
    float b2[3 * NH2];
};

#define FMA_BODY()                                                             \
    do {                                                                       \
        float w1 = __ldg(p);                                                   \
        float w2 = __ldg(p + GS);                                              \
        float w3 = __ldg(p + 2 * GS);                                          \
        float4 xa = *(const float4*)xp;                                        \
        float4 xb = *(const float4*)(xp + 4);                                  \
        p += NH; xp += M;                                                      \
        a1[0] += w1 * xa.x; a1[1] += w1 * xa.y; a1[2] += w1 * xa.z;            \
        a1[3] += w1 * xa.w; a1[4] += w1 * xb.x; a1[5] += w1 * xb.y;            \
        a1[6] += w1 * xb.z; a1[7] += w1 * xb.w;                                \
        a2[0] += w2 * xa.x; a2[1] += w2 * xa.y; a2[2] += w2 * xa.z;            \
        a2[3] += w2 * xa.w; a2[4] += w2 * xb.x; a2[5] += w2 * xb.y;            \
        a2[6] += w2 * xb.z; a2[7] += w2 * xb.w;                                \
        a3[0] += w3 * xa.x; a3[1] += w3 * xa.y; a3[2] += w3 * xa.z;            \
        a3[3] += w3 * xa.w; a3[4] += w3 * xb.x; a3[5] += w3 * xb.y;            \
        a3[6] += w3 * xb.z; a3[7] += w3 * xb.w;                                \
    } while (0)

template <int KLEN, int NH, int GS>
__device__ __forceinline__ void gemm3_t(const float* __restrict__ W, int j, int k0,
                                        const float (*__restrict__ xt)[M],
                                        float* __restrict__ a1,
                                        float* __restrict__ a2,
                                        float* __restrict__ a3) {
    const float* p = W + (size_t)k0 * NH + j;
    const float* xp = &xt[k0][0];
#pragma unroll 4
    for (int k = 0; k < KLEN; ++k) FMA_BODY();
}

__device__ __forceinline__ float cfc_cell(float f1, float f2, float g3) {
    float s = 1.0f / (1.0f + __expf(-g3));
    return tanhf(f1) * (1.0f - s) + s * tanhf(f2);
}

__device__ __forceinline__ void store_part(float (*__restrict__ P)[M],
                                           const float* a1, const float* a2,
                                           const float* a3) {
    *(float4*)&P[0][0] = make_float4(a1[0], a1[1], a1[2], a1[3]);
    *(float4*)&P[0][4] = make_float4(a1[4], a1[5], a1[6], a1[7]);
    *(float4*)&P[1][0] = make_float4(a2[0], a2[1], a2[2], a2[3]);
    *(float4*)&P[1][4] = make_float4(a2[4], a2[5], a2[6], a2[7]);
    *(float4*)&P[2][0] = make_float4(a3[0], a3[1], a3[2], a3[3]);
    *(float4*)&P[2][4] = make_float4(a3[4], a3[5], a3[6], a3[7]);
}

// crew-B-only barrier (warps 8..15, 256 threads)
#define NBAR() asm volatile("bar.sync 1, 256;" ::: "memory")

__global__ __launch_bounds__(BT, 1)
void ncp_main(const float* __restrict__ x, const float* __restrict__ hidden,
              const float* __restrict__ fc_w, const float* __restrict__ fc_b,
              float* __restrict__ out) {
    extern __shared__ char smem_raw[];
    SM* sm = (SM*)smem_raw;
    const int tid = threadIdx.x;
    const int row0 = blockIdx.x * M;

    // ---- init ----
    for (int i = tid; i < 3 * NH0; i += BT) sm->b0[i] = g_B0[i];
    for (int i = tid; i < 3 * NH1; i += BT) sm->b1[i] = g_B1[i];
    for (int i = tid; i < 3 * NH2; i += BT) sm->b2[i] = g_B2[i];
    for (int i = tid; i < OUTD * OUTD; i += BT) {
        int mm = i >> 6, o = i & 63;
        sm->fcT[i] = __ldg(&fc_w[o * OUTD + mm]);
    }
    if (tid < OUTD) sm->fcb[tid] = fc_b[tid];
    for (int i = tid; i < M * 512; i += BT) {
        int r = i >> 9, c = i & 511;
        float v = hidden[(long long)(row0 + r) * 512 + c];
        if (c < NH0)              sm->xt0[0][DIN + c][r] = v;
        else if (c < NH0 + NH1)   sm->xt1[c][r] = v;
        else                      sm->xt2[NH1 + (c - NH0 - NH1)][r] = v;
    }
    if (tid < M) {
        sm->xt0[0][397][tid] = 0.0f; sm->xt0[0][398][tid] = 0.0f; sm->xt0[0][399][tid] = 0.0f;
        sm->xt0[1][397][tid] = 0.0f; sm->xt0[1][398][tid] = 0.0f; sm->xt0[1][399][tid] = 0.0f;
        sm->xt2[243][tid] = 0.0f;
    }
    // preload x(0) into buffer 0 (all threads: 512 * 2 = 1024 floats)
    {
        int r = tid & 7, c = tid >> 3;     // c in 0..63
        const float* xp = x + ((long long)(row0 + r) * Tsz + 0) * DIN;
        sm->xt0[0][c][r]      = __ldg(&xp[c]);
        sm->xt0[0][c + 64][r] = __ldg(&xp[c + 64]);
    }
    __syncthreads();

    // ---- pipelined stage loop ----
    // stage s: crew A computes L0(s) (s<Tsz); crew B computes L1/L2/FC(s-1) (s>=1)
#pragma unroll 1
    for (int s = 0; s <= Tsz; ++s) {
        const int b = s & 1, nb = b ^ 1;
        float nA[M];   // crew A's activated n0, held across barrier1

        if (tid < 256) {
            // ================= crew A =================
            if (s < Tsz) {
                const int j = tid;
                const int xr = tid & 7, xc = tid >> 3;   // xc in 0..31
                // prefetch x(s+1) early (latency hidden under gemm)
                float rx0 = 0.f, rx1 = 0.f, rx2 = 0.f, rx3 = 0.f;
                if (s + 1 < Tsz) {
                    const float* xp = x + ((long long)(row0 + xr) * Tsz + (s + 1)) * DIN;
                    rx0 = __ldg(&xp[xc]);       rx1 = __ldg(&xp[xc + 32]);
                    rx2 = __ldg(&xp[xc + 64]);  rx3 = __ldg(&xp[xc + 96]);
                }
                // main unit: full K = 400
                {
                    float a1[M], a2[M], a3[M];
                    float bf1 = sm->b0[j], bf2 = sm->b0[NH0 + j], bt = sm->b0[2 * NH0 + j];
#pragma unroll
                    for (int r = 0; r < M; ++r) { a1[r] = bf1; a2[r] = bf2; a3[r] = bt; }
                    gemm3_t<CATP0, NH0, GS0>(g_W0, j, 0, sm->xt0[b], a1, a2, a3);
#pragma unroll
                    for (int r = 0; r < M; ++r) nA[r] = cfc_cell(a1[r], a2[r], a3[r]);
                    // h0(s) -> next buffer immediately (A-private until next stage)
                    *(float4*)&sm->xt0[nb][DIN + j][0] = make_float4(nA[0], nA[1], nA[2], nA[3]);
                    *(float4*)&sm->xt0[nb][DIN + j][4] = make_float4(nA[4], nA[5], nA[6], nA[7]);
                }
                // tail: units 256..268, 16 chunks of 25 k on 208 threads
                if (tid < 13 * T0_CH) {
                    int ju = tid % 13, ch = tid / 13;
                    int jt = 256 + ju;
                    float a1[M], a2[M], a3[M];
                    float bf1 = 0.f, bf2 = 0.f, bt = 0.f;
                    if (ch == 0) { bf1 = sm->b0[jt]; bf2 = sm->b0[NH0 + jt]; bt = sm->b0[2 * NH0 + jt]; }
#pragma unroll
                    for (int r = 0; r < M; ++r) { a1[r] = bf1; a2[r] = bf2; a3[r] = bt; }
                    gemm3_t<T0_KL, NH0, GS0>(g_W0, jt, ch * T0_KL, sm->xt0[b], a1, a2, a3);
                    store_part(sm->P0x[ch][ju], a1, a2, a3);
                }
                // store x(s+1) into next buffer
                if (s + 1 < Tsz) {
                    sm->xt0[nb][xc][xr]      = rx0;
                    sm->xt0[nb][xc + 32][xr] = rx1;
                    sm->xt0[nb][xc + 64][xr] = rx2;
                    sm->xt0[nb][xc + 96][xr] = rx3;
                }
            }
        } else {
            // ================= crew B =================
            if (s >= 1) {
                const int btid = tid - 256;
                const int t = s - 1;
                // --- L1 gemm: 716 units (kq*179 + j), K=112 each ---
                {
                    int u = btid;
#pragma unroll 1
                    for (int rep = 0; rep < 3; ++rep) {
                        if (u < 716) {
                            int kq = u / NH1, j = u - kq * NH1;
                            float a1[M], a2[M], a3[M];
                            float bf1 = 0.f, bf2 = 0.f, bt = 0.f;
                            if (kq == 0) { bf1 = sm->b1[j]; bf2 = sm->b1[NH1 + j]; bt = sm->b1[2 * NH1 + j]; }
#pragma unroll
                            for (int r = 0; r < M; ++r) { a1[r] = bf1; a2[r] = bf2; a3[r] = bt; }
                            gemm3_t<112, NH1, GS1>(g_W1, j, kq * 112, sm->xt1, a1, a2, a3);
                            store_part(sm->P.p1[kq][j], a1, a2, a3);
                        }
                        u += 256;
                    }
                }
                NBAR();
                // --- L1 reduce + activate: 179*8 cells on 256 threads ---
                for (int c = btid; c < NH1 * M; c += 256) {
                    int j = c >> 3, r = c & 7;
                    float f1 = sm->P.p1[0][j][0][r] + sm->P.p1[1][j][0][r]
                             + sm->P.p1[2][j][0][r] + sm->P.p1[3][j][0][r];
                    float f2 = sm->P.p1[0][j][1][r] + sm->P.p1[1][j][1][r]
                             + sm->P.p1[2][j][1][r] + sm->P.p1[3][j][1][r];
                    float g3 = sm->P.p1[0][j][2][r] + sm->P.p1[1][j][2][r]
                             + sm->P.p1[2][j][2][r] + sm->P.p1[3][j][2][r];
                    float n = cfc_cell(f1, f2, g3);
                    sm->xt2[j][r] = n;
                    sm->xt1[NH0 + j][r] = n;
                }
                NBAR();
                // --- L2 gemm: 256 units (kq*64 + j), K=61 each ---
                {
                    int kq = btid >> 6, j = btid & 63;
                    float a1[M], a2[M], a3[M];
                    float bf1 = 0.f, bf2 = 0.f, bt = 0.f;
                    if (kq == 0) { bf1 = sm->b2[j]; bf2 = sm->b2[NH2 + j]; bt = sm->b2[2 * NH2 + j]; }
#pragma unroll
                    for (int r = 0; r < M; ++r) { a1[r] = bf1; a2[r] = bf2; a3[r] = bt; }
                    gemm3_t<61, NH2, GS2>(g_W2, j, kq * 61, sm->xt2, a1, a2, a3);
                    store_part(sm->P.p2[kq][j], a1, a2, a3);
                }
                NBAR();
                // --- L2 reduce + activate: 512 cells, 2 per thread ---
#pragma unroll
                for (int rep = 0; rep < 2; ++rep) {
                    int c = btid + rep * 256;
                    int j = c >> 3, r = c & 7;
                    float f1 = 0.f, f2 = 0.f, g3 = 0.f;
#pragma unroll
                    for (int kq = 0; kq < 4; ++kq) {
                        f1 += sm->P.p2[kq][j][0][r];
                        f2 += sm->P.p2[kq][j][1][r];
                        g3 += sm->P.p2[kq][j][2][r];
                    }
                    sm->xt2[NH1 + j][r] = cfc_cell(f1, f2, g3);
                }
                NBAR();
                // --- FC: 512 cells, 2 per thread ---
#pragma unroll
                for (int rep = 0; rep < 2; ++rep) {
                    int c = btid + rep * 256;
                    int r = c >> 6, o = c & 63;
                    float a = sm->fcb[o];
#pragma unroll 8
                    for (int mm = 0; mm < OUTD; ++mm)
                        a += sm->fcT[mm * OUTD + o] * sm->xt2[NH1 + mm][r];
                    out[((long long)(row0 + r) * Tsz + t) * OUTD + o] = a;
                }
            }
        }
        __syncthreads();   // barrier1: A's gemm done, B done reading xt1(n0)

        // ---- boundary: publish n0(s) ----
        if (s < Tsz) {
            if (tid < 256) {
                *(float4*)&sm->xt1[tid][0] = make_float4(nA[0], nA[1], nA[2], nA[3]);
                *(float4*)&sm->xt1[tid][4] = make_float4(nA[4], nA[5], nA[6], nA[7]);
            } else if (tid < 256 + 104) {
                int idx = tid - 256;
                int ju = idx >> 3, r = idx & 7;
                float f1 = 0.f, f2 = 0.f, g3 = 0.f;
#pragma unroll
                for (int ch = 0; ch < T0_CH; ++ch) {
                    f1 += sm->P0x[ch][ju][0][r];
                    f2 += sm->P0x[ch][ju][1][r];
                    g3 += sm->P0x[ch][ju][2][r];
                }
                float n = cfc_cell(f1, f2, g3);
                sm->xt1[256 + ju][r] = n;
                sm->xt0[nb][DIN + 256 + ju][r] = n;
            }
        }
        __syncthreads();   // barrier2: n0(s), h0(s), x(s+1) visible
    }

    // ---- final hidden state (h0(255) lives in xt0[0]) ----
    float* hn = out + PRED_ELEMS;
    for (int i = tid; i < M * 512; i += BT) {
        int r = i >> 9, c = i & 511;
        float v;
        if (c < NH0)            v = sm->xt0[0][DIN + c][r];
        else if (c < NH0 + NH1) v = sm->xt1[c][r];
        else                    v = sm->xt2[NH1 + (c - NH0 - NH1)][r];
        hn[(long long)(row0 + r) * 512 + c] = v;
    }
}

// ---------------- host launcher ----------------
extern "C" void kernel_launch(void* const* d_in, const int* in_sizes, int n_in,
                              void* d_out, int out_size) {
    (void)n_in; (void)out_size;
    const float* x      = (const float*)d_in[0];
    const float* hidden = (const float*)d_in[1];
    const void*  m0     = d_in[2];
    const void*  m1     = d_in[3];
    const void*  m2     = d_in[4];
    const float* ff1_w0 = (const float*)d_in[5];
    const float* ff1_b0 = (const float*)d_in[6];
    const float* ff2_w0 = (const float*)d_in[7];
    const float* ff2_b0 = (const float*)d_in[8];
    const float* ta_w0  = (const float*)d_in[9];
    const float* ta_b0  = (const float*)d_in[10];
    const float* tb_w0  = (const float*)d_in[11];
    const float* tb_b0  = (const float*)d_in[12];
    const float* ff1_w1 = (const float*)d_in[13];
    const float* ff1_b1 = (const float*)d_in[14];
    const float* ff2_w1 = (const float*)d_in[15];
    const float* ff2_b1 = (const float*)d_in[16];
    const float* ta_w1  = (const float*)d_in[17];
    const float* ta_b1  = (const float*)d_in[18];
    const float* tb_w1  = (const float*)d_in[19];
    const float* tb_b1  = (const float*)d_in[20];
    const float* ff1_w2 = (const float*)d_in[21];
    const float* ff1_b2 = (const float*)d_in[22];
    const float* ff2_w2 = (const float*)d_in[23];
    const float* ff2_b2 = (const float*)d_in[24];
    const float* ta_w2  = (const float*)d_in[25];
    const float* ta_b2  = (const float*)d_in[26];
    const float* tb_w2  = (const float*)d_in[27];
    const float* tb_b2  = (const float*)d_in[28];
    const float* fc_w   = (const float*)d_in[29];
    const float* fc_b   = (const float*)d_in[30];
    float* out = (float*)d_out;

    detect_kernel<<<3, 256>>>(m0, in_sizes[2], m1, in_sizes[3], m2, in_sizes[4]);

    prep_all<<<1024, 256>>>(
        ff1_w0, ff2_w0, ta_w0, tb_w0, ff1_b0, ff2_b0, ta_b0, tb_b0,
        ff1_w1, ff2_w1, ta_w1, tb_w1, ff1_b1, ff2_b1, ta_b1, tb_b1,
        ff1_w2, ff2_w2, ta_w2, tb_w2, ff1_b2, ff2_b2, ta_b2, tb_b2,
        m0, m1, m2);

    cudaFuncSetAttribute(ncp_main, cudaFuncAttributeMaxDynamicSharedMemorySize,
                         (int)sizeof(SM));
    ncp_main<<<Bsz / M, BT, sizeof(SM)>>>(x, hidden, fc_w, fc_b, out);
}